// round 17
// baseline (speedup 1.0000x reference)
#include <cuda_runtime.h>
#include <cuda_fp16.h>

#define NN 100000
#define EE 1600000
#define IND 128
#define HIDD 64
#define NC 40

#define NBG 391               // ceil(NN / 256)
#define NTPB 256
#define EGRID 1184
#define ETPB 256
#define EWPB (ETPB / 32)
#define EWARPS (EGRID * EWPB)
#define SCAN_BLKS 391

typedef unsigned long long ull;

// ---------------- device scratch ----------------
__device__ float4   g_h0[NN * 16];
__device__ float4   g_h1[NN * 16];
__device__ float4   g_hacc[NN * 16];
__device__ unsigned g_whh[NN * 32];   // wh rows, half2-packed
__device__ float    g_ssrc[NN];
__device__ float    g_sdst[NN];
__device__ float    g_pmax_s[NBG];
__device__ float    g_pmax_d[NBG];
__device__ float    g_psum[EGRID];
__device__ int      g_is64;
__device__ int2     g_epack[EE];
__device__ int      g_deg[NN];
__device__ int      g_rp[NN];
__device__ int      g_btot[SCAN_BLKS];
__device__ int      g_boff[SCAN_BLKS];
__device__ int      g_rowptr[NN + 1];
__device__ int      g_cursor[NN];
__device__ int      g_csrc[EE];

// ---------------- helpers ----------------
__device__ __forceinline__ float eluf(float x) { return x > 0.f ? x : (expf(x) - 1.f); }

__device__ __forceinline__ void mma16816(float* c, const unsigned* a, unsigned b0, unsigned b1) {
    asm volatile(
        "mma.sync.aligned.m16n8k16.row.col.f32.f16.f16.f32 "
        "{%0,%1,%2,%3}, {%4,%5,%6,%7}, {%8,%9}, {%0,%1,%2,%3};"
        : "+f"(c[0]), "+f"(c[1]), "+f"(c[2]), "+f"(c[3])
        : "r"(a[0]), "r"(a[1]), "r"(a[2]), "r"(a[3]), "r"(b0), "r"(b1));
}

// ---------------- dtype detect + zero degrees ----------------
__global__ void k_detect_zdeg(const int* __restrict__ ei32) {
    int i = blockIdx.x * blockDim.x + threadIdx.x;
    if (i < NN) g_deg[i] = 0;
    if (blockIdx.x == 0) {
        int nz = 0;
        for (int k = threadIdx.x; k < 1024; k += blockDim.x)
            if (ei32[2 * k + 1] != 0) nz = 1;
        int cnt = __syncthreads_count(nz);
        if (threadIdx.x == 0) g_is64 = (cnt == 0) ? 1 : 0;
    }
}

// ---------------- CSR build ----------------
__global__ void k_hist(const void* __restrict__ ei) {
    int is64 = g_is64;
    int e = blockIdx.x * blockDim.x + threadIdx.x;
    if (e >= EE) return;
    int s, d;
    if (is64) {
        s = (int)((const long long*)ei)[e];
        d = (int)((const long long*)ei)[EE + e];
    } else {
        s = ((const int*)ei)[e];
        d = ((const int*)ei)[EE + e];
    }
    s = min(max(s, 0), NN - 1);
    d = min(max(d, 0), NN - 1);
    g_epack[e] = make_int2(s, d);
    atomicAdd(&g_deg[d], 1);
}

__global__ void k_scan1() {
    __shared__ int sm[256];
    int i = blockIdx.x * 256 + threadIdx.x;
    int v = (i < NN) ? g_deg[i] : 0;
    sm[threadIdx.x] = v;
    __syncthreads();
    for (int off = 1; off < 256; off <<= 1) {
        int t = (threadIdx.x >= off) ? sm[threadIdx.x - off] : 0;
        __syncthreads();
        sm[threadIdx.x] += t;
        __syncthreads();
    }
    int incl = sm[threadIdx.x];
    if (i < NN) g_rp[i] = incl - v;
    if (threadIdx.x == 255) g_btot[blockIdx.x] = incl;
}

__global__ void k_scan2() {
    __shared__ int sm[512];
    int tid = threadIdx.x;
    int v = (tid < SCAN_BLKS) ? g_btot[tid] : 0;
    sm[tid] = v;
    __syncthreads();
    for (int off = 1; off < 512; off <<= 1) {
        int t = (tid >= off) ? sm[tid - off] : 0;
        __syncthreads();
        sm[tid] += t;
        __syncthreads();
    }
    if (tid < SCAN_BLKS) g_boff[tid] = sm[tid] - v;
}

__global__ void k_scan3() {
    int i = blockIdx.x * blockDim.x + threadIdx.x;
    if (i < NN) {
        int rp = g_rp[i] + g_boff[i >> 8];
        g_rowptr[i] = rp;
        g_cursor[i] = rp;
    }
    if (i == 0) g_rowptr[NN] = EE;
}

__global__ void k_scat() {
    int e = blockIdx.x * blockDim.x + threadIdx.x;
    if (e >= EE) return;
    int2 sd = g_epack[e];
    int pos = atomicAdd(&g_cursor[sd.y], 1);
    g_csrc[pos] = sd.x;
}

#define HSTRIDE 72

// ---------------- embedding via tensor cores ----------------
__global__ void __launch_bounds__(NTPB, 2) k_emb(const float* __restrict__ x,
                                                 const float* __restrict__ w,
                                                 const float* __restrict__ b) {
    __shared__ __half sH[256 * HSTRIDE];
    __shared__ __half sWt[64 * HSTRIDE];
    __shared__ float sb[HIDD];
    int tid = threadIdx.x;
    if (tid < HIDD) sb[tid] = b[tid];

    int node = blockIdx.x * 256 + tid;
    int nc = (node < NN) ? node : 0;

    int wp = tid >> 5;
    int lane = tid & 31;
    int grp = lane >> 2;
    int qid = lane & 3;

    float c[2][8][4];
#pragma unroll
    for (int mt = 0; mt < 2; mt++)
#pragma unroll
        for (int nt = 0; nt < 8; nt++)
#pragma unroll
            for (int q = 0; q < 4; q++) c[mt][nt][q] = 0.f;

    for (int half = 0; half < 2; half++) {
        __syncthreads();
        for (int i = tid; i < 64 * 64; i += NTPB) {
            int k = i >> 6, n = i & 63;
            sWt[n * HSTRIDE + k] = __float2half(w[(half * 64 + k) * HIDD + n]);
        }
        {
            const float4* xr = reinterpret_cast<const float4*>(x + (size_t)nc * IND + half * 64);
            __half2* dst = reinterpret_cast<__half2*>(sH + tid * HSTRIDE);
#pragma unroll
            for (int k4 = 0; k4 < 16; k4++) {
                float4 v = xr[k4];
                dst[2 * k4]     = __floats2half2_rn(v.x, v.y);
                dst[2 * k4 + 1] = __floats2half2_rn(v.z, v.w);
            }
        }
        __syncthreads();

#pragma unroll
        for (int kc = 0; kc < 4; kc++) {
            int k0 = kc * 16 + 2 * qid;
            unsigned a[2][4];
#pragma unroll
            for (int mt = 0; mt < 2; mt++) {
                const __half* base = sH + (wp * 32 + mt * 16 + grp) * HSTRIDE;
                a[mt][0] = *reinterpret_cast<const unsigned*>(base + k0);
                a[mt][1] = *reinterpret_cast<const unsigned*>(base + 8 * HSTRIDE + k0);
                a[mt][2] = *reinterpret_cast<const unsigned*>(base + k0 + 8);
                a[mt][3] = *reinterpret_cast<const unsigned*>(base + 8 * HSTRIDE + k0 + 8);
            }
#pragma unroll
            for (int nt = 0; nt < 8; nt++) {
                const __half* bb = sWt + (nt * 8 + grp) * HSTRIDE + k0;
                unsigned b0 = *reinterpret_cast<const unsigned*>(bb);
                unsigned b1 = *reinterpret_cast<const unsigned*>(bb + 8);
                mma16816(c[0][nt], a[0], b0, b1);
                mma16816(c[1][nt], a[1], b0, b1);
            }
        }
    }

    float2* h0f2 = reinterpret_cast<float2*>(g_h0);
#pragma unroll
    for (int mt = 0; mt < 2; mt++) {
        int row0 = wp * 32 + mt * 16 + grp;
        int row1 = row0 + 8;
        int node0 = blockIdx.x * 256 + row0;
        int node1 = blockIdx.x * 256 + row1;
#pragma unroll
        for (int nt = 0; nt < 8; nt++) {
            int col = nt * 8 + 2 * qid;
            float b0v = sb[col], b1v = sb[col + 1];
            int pidx = nt * 4 + qid;
            if (node0 < NN)
                h0f2[(size_t)node0 * 32 + pidx] = make_float2(c[mt][nt][0] + b0v, c[mt][nt][1] + b1v);
            if (node1 < NN)
                h0f2[(size_t)node1 * 32 + pidx] = make_float2(c[mt][nt][2] + b0v, c[mt][nt][3] + b1v);
        }
    }
}

// ---------------- per-layer GEMM via tensor cores ----------------
__global__ void __launch_bounds__(NTPB, 2) k_gemm_s(int layer,
                                                    const float* __restrict__ W,
                                                    const float* __restrict__ avec) {
    __shared__ __half sH[256 * HSTRIDE];
    __shared__ __half sWt[64 * HSTRIDE];
    __shared__ float sa[2 * HIDD];
    __shared__ float sInv;
    int tid = threadIdx.x;

    if (tid < 2 * HIDD) sa[tid] = avec[tid];

    if (layer) {
        float t = 0.0f;
        for (int i = tid; i < EGRID; i += NTPB) t += g_psum[i];
#pragma unroll
        for (int o = 16; o; o >>= 1) t += __shfl_xor_sync(0xffffffffu, t, o);
        __shared__ float smr[8];
        if ((tid & 31) == 0) smr[tid >> 5] = t;
        __syncthreads();
        if (tid == 0) {
            float s = 0.0f;
            for (int i = 0; i < 8; i++) s += smr[i];
            sInv = (s > 0.0f) ? (1.0f / s) : 0.0f;
        }
        __syncthreads();
    }
    float inv = layer ? sInv : 1.0f;

    for (int i = tid; i < HIDD * HIDD; i += NTPB) {
        int k = i >> 6, n = i & 63;
        sWt[n * HSTRIDE + k] = __float2half(W[i]);
    }

    {
        int node = blockIdx.x * 256 + tid;
        int nc = (node < NN) ? node : 0;
        const float4* hr = (layer ? g_h1 : g_h0) + (size_t)nc * 16;
        __half2* dst = reinterpret_cast<__half2*>(sH + tid * HSTRIDE);
#pragma unroll
        for (int k4 = 0; k4 < 16; k4++) {
            float4 v = hr[k4];
            if (layer) {
                v.x = eluf(v.x * inv); v.y = eluf(v.y * inv);
                v.z = eluf(v.z * inv); v.w = eluf(v.w * inv);
            }
            dst[2 * k4]     = __floats2half2_rn(v.x, v.y);
            dst[2 * k4 + 1] = __floats2half2_rn(v.z, v.w);
        }
    }
    __syncthreads();

    int w = tid >> 5;
    int lane = tid & 31;
    int grp = lane >> 2;
    int qid = lane & 3;

    float c[2][8][4];
#pragma unroll
    for (int mt = 0; mt < 2; mt++)
#pragma unroll
        for (int nt = 0; nt < 8; nt++)
#pragma unroll
            for (int q = 0; q < 4; q++) c[mt][nt][q] = 0.f;

#pragma unroll
    for (int kc = 0; kc < 4; kc++) {
        int k0 = kc * 16 + 2 * qid;
        unsigned a[2][4];
#pragma unroll
        for (int mt = 0; mt < 2; mt++) {
            const __half* base = sH + (w * 32 + mt * 16 + grp) * HSTRIDE;
            a[mt][0] = *reinterpret_cast<const unsigned*>(base + k0);
            a[mt][1] = *reinterpret_cast<const unsigned*>(base + 8 * HSTRIDE + k0);
            a[mt][2] = *reinterpret_cast<const unsigned*>(base + k0 + 8);
            a[mt][3] = *reinterpret_cast<const unsigned*>(base + 8 * HSTRIDE + k0 + 8);
        }
#pragma unroll
        for (int nt = 0; nt < 8; nt++) {
            const __half* bb = sWt + (nt * 8 + grp) * HSTRIDE + k0;
            unsigned b0 = *reinterpret_cast<const unsigned*>(bb);
            unsigned b1 = *reinterpret_cast<const unsigned*>(bb + 8);
            mma16816(c[0][nt], a[0], b0, b1);
            mma16816(c[1][nt], a[1], b0, b1);
        }
    }

    float rmax_s = -3.4e38f, rmax_d = -3.4e38f;
#pragma unroll
    for (int mt = 0; mt < 2; mt++) {
        float ss0 = 0.f, ss1 = 0.f, sd0 = 0.f, sd1 = 0.f;
#pragma unroll
        for (int nt = 0; nt < 8; nt++) {
            int col = nt * 8 + 2 * qid;
            float as0 = sa[col], as1 = sa[col + 1];
            float ad0 = sa[HIDD + col], ad1 = sa[HIDD + col + 1];
            ss0 += c[mt][nt][0] * as0 + c[mt][nt][1] * as1;
            sd0 += c[mt][nt][0] * ad0 + c[mt][nt][1] * ad1;
            ss1 += c[mt][nt][2] * as0 + c[mt][nt][3] * as1;
            sd1 += c[mt][nt][2] * ad0 + c[mt][nt][3] * ad1;
        }
        ss0 += __shfl_xor_sync(0xffffffffu, ss0, 1);
        ss0 += __shfl_xor_sync(0xffffffffu, ss0, 2);
        sd0 += __shfl_xor_sync(0xffffffffu, sd0, 1);
        sd0 += __shfl_xor_sync(0xffffffffu, sd0, 2);
        ss1 += __shfl_xor_sync(0xffffffffu, ss1, 1);
        ss1 += __shfl_xor_sync(0xffffffffu, ss1, 2);
        sd1 += __shfl_xor_sync(0xffffffffu, sd1, 1);
        sd1 += __shfl_xor_sync(0xffffffffu, sd1, 2);

        int row0 = w * 32 + mt * 16 + grp;
        int row1 = row0 + 8;
        int node0 = blockIdx.x * 256 + row0;
        int node1 = blockIdx.x * 256 + row1;

        if (qid == 0) {
            if (node0 < NN) { g_ssrc[node0] = ss0; g_sdst[node0] = sd0; }
            if (node1 < NN) { g_ssrc[node1] = ss1; g_sdst[node1] = sd1; }
        }
        if (node0 < NN) { rmax_s = fmaxf(rmax_s, ss0); rmax_d = fmaxf(rmax_d, sd0); }
        if (node1 < NN) { rmax_s = fmaxf(rmax_s, ss1); rmax_d = fmaxf(rmax_d, sd1); }

#pragma unroll
        for (int nt = 0; nt < 8; nt++) {
            int pidx = qid + nt * 4;
            if (node0 < NN) {
                __half2 h0 = __floats2half2_rn(c[mt][nt][0], c[mt][nt][1]);
                g_whh[(size_t)node0 * 32 + pidx] = *reinterpret_cast<unsigned*>(&h0);
            }
            if (node1 < NN) {
                __half2 h1 = __floats2half2_rn(c[mt][nt][2], c[mt][nt][3]);
                g_whh[(size_t)node1 * 32 + pidx] = *reinterpret_cast<unsigned*>(&h1);
            }
        }
    }

#pragma unroll
    for (int o = 16; o; o >>= 1) {
        rmax_s = fmaxf(rmax_s, __shfl_xor_sync(0xffffffffu, rmax_s, o));
        rmax_d = fmaxf(rmax_d, __shfl_xor_sync(0xffffffffu, rmax_d, o));
    }
    __shared__ float sms[8], smd[8];
    if (lane == 0) { sms[w] = rmax_s; smd[w] = rmax_d; }
    __syncthreads();
    if (tid == 0) {
        float a = sms[0], b = smd[0];
        for (int i = 1; i < 8; i++) { a = fmaxf(a, sms[i]); b = fmaxf(b, smd[i]); }
        g_pmax_s[blockIdx.x] = a;
        g_pmax_d[blockIdx.x] = b;
    }
}

// ---------------- CSR aggregation: unrolled broadcast loop, 4 acc chains ----------------
__global__ void __launch_bounds__(ETPB) k_aggr(int layer) {
    __shared__ float sB;
    {
        float a = -3.4e38f, b = -3.4e38f;
        for (int i = threadIdx.x; i < NBG; i += ETPB) {
            a = fmaxf(a, g_pmax_s[i]);
            b = fmaxf(b, g_pmax_d[i]);
        }
#pragma unroll
        for (int o = 16; o; o >>= 1) {
            a = fmaxf(a, __shfl_xor_sync(0xffffffffu, a, o));
            b = fmaxf(b, __shfl_xor_sync(0xffffffffu, b, o));
        }
        __shared__ float ra[EWPB], rb[EWPB];
        if ((threadIdx.x & 31) == 0) { ra[threadIdx.x >> 5] = a; rb[threadIdx.x >> 5] = b; }
        __syncthreads();
        if (threadIdx.x == 0) {
            float ma = ra[0], mb = rb[0];
            for (int i = 1; i < EWPB; i++) { ma = fmaxf(ma, ra[i]); mb = fmaxf(mb, rb[i]); }
            sB = ma + mb;
        }
        __syncthreads();
    }
    const float B = sB;

    int lane = threadIdx.x & 31;
    int wid = threadIdx.x >> 5;

    float2* acc2 = reinterpret_cast<float2*>(layer ? g_hacc : g_h1);

    float psum = 0.0f;
    for (int d = blockIdx.x * EWPB + wid; d < NN; d += EWARPS) {
        int beg = g_rowptr[d];
        int end = g_rowptr[d + 1];
        float sdd = g_sdst[d];
        float2 A[4];
#pragma unroll
        for (int q = 0; q < 4; q++) A[q] = make_float2(0.f, 0.f);

        for (int c = beg; c < end; c += 32) {
            int e = c + lane;
            int s = 0; float p = 0.f;
            if (e < end) {
                s = g_csrc[e];
                float sc = g_ssrc[s] + sdd;
                if (sc > 0.f) p = expf(sc - B);
            }
            psum += p;

            int nE = end - c;   // >=1; lanes beyond have p=0
            __syncwarp();
#pragma unroll
            for (int j = 0; j < 32; j++) {
                float pj = __shfl_sync(0xffffffffu, p, j);
                int sj = __shfl_sync(0xffffffffu, s, j);
                if (j < nE && pj != 0.f) {
                    unsigned u = g_whh[(size_t)sj * 32 + lane];
                    float2 xv = __half22float2(*reinterpret_cast<__half2*>(&u));
                    A[j & 3].x += pj * xv.x;
                    A[j & 3].y += pj * xv.y;
                }
            }
        }

        float2 R;
        R.x = (A[0].x + A[1].x) + (A[2].x + A[3].x);
        R.y = (A[0].y + A[1].y) + (A[2].y + A[3].y);
        acc2[(size_t)d * 32 + lane] = R;
    }

#pragma unroll
    for (int o = 16; o; o >>= 1) psum += __shfl_xor_sync(0xffffffffu, psum, o);
    __shared__ float sm2[EWPB];
    if (lane == 0) sm2[wid] = psum;
    __syncthreads();
    if (threadIdx.x == 0) {
        float t = 0.0f;
        for (int i = 0; i < EWPB; i++) t += sm2[i];
        g_psum[blockIdx.x] = t;
    }
}

// ---------------- output head via tensor cores ----------------
__global__ void __launch_bounds__(NTPB, 2) k_out(const float* __restrict__ W,
                                                 const float* __restrict__ b,
                                                 float* __restrict__ out) {
    __shared__ __half sH[256 * HSTRIDE];
    __shared__ __half sWt[NC * HSTRIDE];
    __shared__ float sb[NC];
    __shared__ float sInv;
    int tid = threadIdx.x;
    if (tid < NC) sb[tid] = b[tid];
    {
        float t = 0.0f;
        for (int i = tid; i < EGRID; i += NTPB) t += g_psum[i];
#pragma unroll
        for (int o = 16; o; o >>= 1) t += __shfl_xor_sync(0xffffffffu, t, o);
        __shared__ float smr[8];
        if ((tid & 31) == 0) smr[tid >> 5] = t;
        __syncthreads();
        if (tid == 0) {
            float s = 0.0f;
            for (int i = 0; i < 8; i++) s += smr[i];
            sInv = (s > 0.0f) ? (1.0f / s) : 0.0f;
        }
        __syncthreads();
    }
    float inv = sInv;

    for (int i = tid; i < HIDD * NC; i += NTPB) {
        int k = i / NC, n = i % NC;
        sWt[n * HSTRIDE + k] = __float2half(W[i]);
    }

    {
        int node = blockIdx.x * 256 + tid;
        int nc = (node < NN) ? node : 0;
        const float4* hr = g_hacc + (size_t)nc * 16;
        __half2* dst = reinterpret_cast<__half2*>(sH + tid * HSTRIDE);
#pragma unroll
        for (int k4 = 0; k4 < 16; k4++) {
            float4 v = hr[k4];
            v.x = eluf(v.x * inv); v.y = eluf(v.y * inv);
            v.z = eluf(v.z * inv); v.w = eluf(v.w * inv);
            dst[2 * k4]     = __floats2half2_rn(v.x, v.y);
            dst[2 * k4 + 1] = __floats2half2_rn(v.z, v.w);
        }
    }
    __syncthreads();

    int wp = tid >> 5;
    int lane = tid & 31;
    int grp = lane >> 2;
    int qid = lane & 3;

    float c[2][5][4];
#pragma unroll
    for (int mt = 0; mt < 2; mt++)
#pragma unroll
        for (int nt = 0; nt < 5; nt++)
#pragma unroll
            for (int q = 0; q < 4; q++) c[mt][nt][q] = 0.f;

#pragma unroll
    for (int kc = 0; kc < 4; kc++) {
        int k0 = kc * 16 + 2 * qid;
        unsigned a[2][4];
#pragma unroll
        for (int mt = 0; mt < 2; mt++) {
            const __half* base = sH + (wp * 32 + mt * 16 + grp) * HSTRIDE;
            a[mt][0] = *reinterpret_cast<const unsigned*>(base + k0);
            a[mt][1] = *reinterpret_cast<const unsigned*>(base + 8 * HSTRIDE + k0);
            a[mt][2] = *reinterpret_cast<const unsigned*>(base + k0 + 8);
            a[mt][3] = *reinterpret_cast<const unsigned*>(base + 8 * HSTRIDE + k0 + 8);
        }
#pragma unroll
        for (int nt = 0; nt < 5; nt++) {
            const __half* bb = sWt + (nt * 8 + grp) * HSTRIDE + k0;
            unsigned b0 = *reinterpret_cast<const unsigned*>(bb);
            unsigned b1 = *reinterpret_cast<const unsigned*>(bb + 8);
            mma16816(c[0][nt], a[0], b0, b1);
            mma16816(c[1][nt], a[1], b0, b1);
        }
    }

    float2* of2 = reinterpret_cast<float2*>(out);
#pragma unroll
    for (int mt = 0; mt < 2; mt++) {
        int row0 = wp * 32 + mt * 16 + grp;
        int row1 = row0 + 8;
        int node0 = blockIdx.x * 256 + row0;
        int node1 = blockIdx.x * 256 + row1;

        float v0[10], v1[10];
#pragma unroll
        for (int nt = 0; nt < 5; nt++) {
            int col = nt * 8 + 2 * qid;
            float b0v = sb[col], b1v = sb[col + 1];
            v0[2 * nt]     = c[mt][nt][0] + b0v;
            v0[2 * nt + 1] = c[mt][nt][1] + b1v;
            v1[2 * nt]     = c[mt][nt][2] + b0v;
            v1[2 * nt + 1] = c[mt][nt][3] + b1v;
        }
        float m0 = -3.4e38f, m1 = -3.4e38f;
#pragma unroll
        for (int j = 0; j < 10; j++) {
            v0[j] = (v0[j] > 0.f) ? v0[j] : (expf(v0[j]) - 1.f);
            v1[j] = (v1[j] > 0.f) ? v1[j] : (expf(v1[j]) - 1.f);
            m0 = fmaxf(m0, v0[j]);
            m1 = fmaxf(m1, v1[j]);
        }
        m0 = fmaxf(m0, __shfl_xor_sync(0xffffffffu, m0, 1));
        m0 = fmaxf(m0, __shfl_xor_sync(0xffffffffu, m0, 2));
        m1 = fmaxf(m1, __shfl_xor_sync(0xffffffffu, m1, 1));
        m1 = fmaxf(m1, __shfl_xor_sync(0xffffffffu, m1, 2));

        float se0 = 0.f, se1 = 0.f;
#pragma unroll
        for (int j = 0; j < 10; j++) {
            se0 += expf(v0[j] - m0);
            se1 += expf(v1[j] - m1);
        }
        se0 += __shfl_xor_sync(0xffffffffu, se0, 1);
        se0 += __shfl_xor_sync(0xffffffffu, se0, 2);
        se1 += __shfl_xor_sync(0xffffffffu, se1, 1);
        se1 += __shfl_xor_sync(0xffffffffu, se1, 2);
        float lse0 = m0 + logf(se0);
        float lse1 = m1 + logf(se1);

#pragma unroll
        for (int nt = 0; nt < 5; nt++) {
            int pidx = nt * 4 + qid;
            if (node0 < NN)
                of2[(size_t)node0 * 20 + pidx] = make_float2(v0[2 * nt] - lse0, v0[2 * nt + 1] - lse0);
            if (node1 < NN)
                of2[(size_t)node1 * 20 + pidx] = make_float2(v1[2 * nt] - lse1, v1[2 * nt + 1] - lse1);
        }
    }
}

// ---------------- launch ----------------
extern "C" void kernel_launch(void* const* d_in, const int* in_sizes, int n_in,
                              void* d_out, int out_size) {
    const float* x      = (const float*)d_in[0];
    const void*  ei     = (const void*)d_in[1];
    const float* emb_w  = (const float*)d_in[2];
    const float* emb_b  = (const float*)d_in[3];
    const float* Ws     = (const float*)d_in[4];
    const float* attn_a = (const float*)d_in[5];
    const float* out_w  = (const float*)d_in[6];
    const float* out_b  = (const float*)d_in[7];
    float* out          = (float*)d_out;

    (void)in_sizes; (void)n_in; (void)out_size;

    const int EB = (EE + 255) / 256;
    const int NB = (NN + 255) / 256;

    k_emb<<<NBG, NTPB>>>(x, emb_w, emb_b);
    k_detect_zdeg<<<NB, 256>>>((const int*)ei);
    k_hist<<<EB, 256>>>(ei);
    k_scan1<<<SCAN_BLKS, 256>>>();
    k_scan2<<<1, 512>>>();
    k_gemm_s<<<NBG, NTPB>>>(0, Ws, attn_a);
    k_scan3<<<NB, 256>>>();
    k_scat<<<EB, 256>>>();
    k_aggr<<<EGRID, ETPB>>>(0);
    k_gemm_s<<<NBG, NTPB>>>(1, Ws + HIDD * HIDD, attn_a + 2 * HIDD);
    k_aggr<<<EGRID, ETPB>>>(1);
    k_out<<<NBG, NTPB>>>(out_w, out_b, out);
}